// round 1
// baseline (speedup 1.0000x reference)
#include <cuda_runtime.h>
#include <math.h>

// Problem constants
#define TT 2048
#define DD 1024
#define FF 2048
#define CC 4
#define EE 4
#define NEXP 16
#define EPSL 1e-5f

#define BM 64
#define BN 64
#define BK 16

// ---------------- device scratch (static, no allocation) ----------------
__device__ float g_H[16ULL*2048ULL*2048ULL];   // activated hidden per expert slot [idx][row][F]
__device__ float g_Z[16ULL*2048ULL*1024ULL];   // expert output rows (residual, then LN in place)
__device__ int   g_cnt[NEXP];
__device__ int   g_tok[NEXP*TT];
__device__ float g_mu[TT];
__device__ float g_rstd[TT];
__device__ int   g_sel[TT*2];       // selected cluster ids per token
__device__ float g_gate[TT*2];      // renormalized cluster gates
__device__ int   g_islot[TT*4];     // per token: 2 clusters x 2 experts -> expert slot
__device__ int   g_ipos[TT*4];      // position in that expert's token list
__device__ float g_icoef[TT*4];     // expert combine coefficient

// ---------------- helpers ----------------
__device__ __forceinline__ void block_meanvar_256(float s, float s2, float* rbuf,
                                                  float& mu, float& rs)
{
    int tid = threadIdx.x, lane = tid & 31, w = tid >> 5;
    __syncthreads();  // protect rbuf reuse across calls
    #pragma unroll
    for (int o = 16; o; o >>= 1) {
        s  += __shfl_down_sync(0xffffffffu, s,  o);
        s2 += __shfl_down_sync(0xffffffffu, s2, o);
    }
    if (lane == 0) { rbuf[w] = s; rbuf[8 + w] = s2; }
    __syncthreads();
    if (tid == 0) {
        float S = 0.f, S2 = 0.f;
        #pragma unroll
        for (int ww = 0; ww < 8; ww++) { S += rbuf[ww]; S2 += rbuf[8 + ww]; }
        float m = S / (float)DD;
        rbuf[16] = m;
        rbuf[17] = rsqrtf(S2 / (float)DD - m * m + EPSL);
    }
    __syncthreads();
    mu = rbuf[16];
    rs = rbuf[17];
}

// ---------------- kernels ----------------
__global__ void zero_cnt_kernel()
{
    if (threadIdx.x < NEXP) g_cnt[threadIdx.x] = 0;
}

__global__ void routing_kernel(const float* __restrict__ x,
                               const float* __restrict__ Wrc, const float* __restrict__ brc,
                               const float* __restrict__ Wre, const float* __restrict__ bre)
{
    int t = blockIdx.x;
    __shared__ float xs[DD];
    __shared__ float rbuf[16];
    __shared__ float lgs[20];
    int tid = threadIdx.x;          // 128 threads
    int lane = tid & 31, wid = tid >> 5;

    float s = 0.f, s2 = 0.f;
    for (int d = tid; d < DD; d += 128) {
        float v = x[(size_t)t * DD + d];
        xs[d] = v; s += v; s2 += v * v;
    }
    #pragma unroll
    for (int o = 16; o; o >>= 1) {
        s  += __shfl_down_sync(0xffffffffu, s,  o);
        s2 += __shfl_down_sync(0xffffffffu, s2, o);
    }
    if (lane == 0) { rbuf[wid] = s; rbuf[8 + wid] = s2; }
    __syncthreads();
    if (tid == 0) {
        float S  = rbuf[0] + rbuf[1] + rbuf[2] + rbuf[3];
        float S2 = rbuf[8] + rbuf[9] + rbuf[10] + rbuf[11];
        float mu = S / (float)DD;
        float var = S2 / (float)DD - mu * mu;
        g_mu[t] = mu;
        g_rstd[t] = rsqrtf(var + EPSL);
    }

    // 20 dot products: 4 cluster-router cols + 16 expert-router cols
    for (int v = wid; v < 20; v += 4) {
        float acc = 0.f;
        if (v < CC) {
            for (int d = lane; d < DD; d += 32) acc += xs[d] * Wrc[d * CC + v];
        } else {
            int cc = (v - 4) >> 2, e = (v - 4) & 3;
            const float* wp = Wre + (size_t)cc * DD * EE + e;
            for (int d = lane; d < DD; d += 32) acc += xs[d] * wp[d * EE];
        }
        #pragma unroll
        for (int o = 16; o; o >>= 1) acc += __shfl_down_sync(0xffffffffu, acc, o);
        if (lane == 0) lgs[v] = acc;
    }
    __syncthreads();

    if (tid == 0) {
        // cluster softmax + top-2 (ties -> lowest index, matching lax.top_k)
        float p[CC];
        float mx = -1e30f;
        for (int c = 0; c < CC; c++) { p[c] = lgs[c] + brc[c]; mx = fmaxf(mx, p[c]); }
        float ss = 0.f;
        for (int c = 0; c < CC; c++) { p[c] = expf(p[c] - mx); ss += p[c]; }
        for (int c = 0; c < CC; c++) p[c] /= ss;
        int i0 = 0;
        for (int c = 1; c < CC; c++) if (p[c] > p[i0]) i0 = c;
        int i1 = -1;
        for (int c = 0; c < CC; c++) if (c != i0 && (i1 < 0 || p[c] > p[i1])) i1 = c;
        float swt = p[i0] + p[i1];
        int sel[2] = { i0, i1 };
        float gv[2] = { p[i0] / swt, p[i1] / swt };

        for (int sI = 0; sI < 2; sI++) {
            int cc = sel[sI];
            g_sel[t * 2 + sI]  = cc;
            g_gate[t * 2 + sI] = gv[sI];
            float el[EE];
            for (int e = 0; e < EE; e++) el[e] = lgs[4 + cc * 4 + e] + bre[cc * EE + e];
            int e0 = 0;
            for (int e = 1; e < EE; e++) if (el[e] > el[e0]) e0 = e;
            int e1 = -1;
            for (int e = 0; e < EE; e++) if (e != e0 && (e1 < 0 || el[e] > el[e1])) e1 = e;
            float z = expf(el[e1] - el[e0]);            // softmax over the 2 selected logits
            float w0 = 1.f / (1.f + z), w1 = z / (1.f + z);
            int   eS[2] = { e0, e1 };
            float wS[2] = { w0, w1 };
            for (int q = 0; q < 2; q++) {
                int slot = cc * EE + eS[q];
                int pos = atomicAdd(&g_cnt[slot], 1);
                g_tok[slot * TT + pos] = t;
                g_islot[t * 4 + sI * 2 + q] = slot;
                g_ipos [t * 4 + sI * 2 + q] = pos;
                g_icoef[t * 4 + sI * 2 + q] = wS[q];
            }
        }
    }
}

// GEMM1: H = act( LN_in(x_gathered) @ W1 [, @ W2] )   -> g_H (activated)
__global__ void __launch_bounds__(256) gemm1_kernel(
    const float* __restrict__ x,
    const float* __restrict__ W1, const float* __restrict__ W2,
    const float* __restrict__ ling, const float* __restrict__ linb)
{
    int idx = blockIdx.z;
    int Nt = g_cnt[idx];
    int m0 = blockIdx.y * BM;
    if (m0 >= Nt) return;
    int n0 = blockIdx.x * BN;
    int j = idx & 3;
    int act = j % 3;                 // 0: swiglu, 1: gelu(exact), 2: relu
    bool dual = (act == 0);
    const float* W1b = W1 + (size_t)idx * DD * FF;
    const float* W2b = W2 + (size_t)idx * DD * FF;
    const float* gp = ling + idx * DD;
    const float* bp = linb + idx * DD;

    __shared__ float As[BK][BM + 1];
    __shared__ float B1s[BK][BN];
    __shared__ float B2s[BK][BN];
    __shared__ int   stok[BM];
    __shared__ float smu[BM], srs[BM];

    int tid = threadIdx.x;
    if (tid < BM) {
        int m = m0 + tid;
        int tk = (m < Nt) ? g_tok[idx * TT + m] : 0;
        stok[tid] = tk;
        smu[tid] = g_mu[tk];
        srs[tid] = g_rstd[tk];
    }

    float acc1[4][4] = {};
    float acc2[4][4] = {};
    int ty = tid >> 4, tx = tid & 15;

    for (int k0 = 0; k0 < DD; k0 += BK) {
        __syncthreads();
        #pragma unroll
        for (int it = 0; it < 4; it++) {
            int m = (tid >> 4) + it * 16;
            int k = tid & 15;
            float v = x[(size_t)stok[m] * DD + k0 + k];
            As[k][m] = (v - smu[m]) * srs[m] * gp[k0 + k] + bp[k0 + k];
        }
        #pragma unroll
        for (int it = 0; it < 4; it++) {
            int k = (tid >> 6) + it * 4;
            int n = tid & 63;
            B1s[k][n] = W1b[(size_t)(k0 + k) * FF + n0 + n];
        }
        if (dual) {
            #pragma unroll
            for (int it = 0; it < 4; it++) {
                int k = (tid >> 6) + it * 4;
                int n = tid & 63;
                B2s[k][n] = W2b[(size_t)(k0 + k) * FF + n0 + n];
            }
        }
        __syncthreads();
        #pragma unroll
        for (int k = 0; k < BK; k++) {
            float a[4], b1[4], b2[4];
            #pragma unroll
            for (int i = 0; i < 4; i++) a[i] = As[k][ty * 4 + i];
            #pragma unroll
            for (int i = 0; i < 4; i++) b1[i] = B1s[k][tx * 4 + i];
            if (dual) {
                #pragma unroll
                for (int i = 0; i < 4; i++) b2[i] = B2s[k][tx * 4 + i];
                #pragma unroll
                for (int mi = 0; mi < 4; mi++)
                    #pragma unroll
                    for (int ni = 0; ni < 4; ni++) {
                        acc1[mi][ni] += a[mi] * b1[ni];
                        acc2[mi][ni] += a[mi] * b2[ni];
                    }
            } else {
                #pragma unroll
                for (int mi = 0; mi < 4; mi++)
                    #pragma unroll
                    for (int ni = 0; ni < 4; ni++)
                        acc1[mi][ni] += a[mi] * b1[ni];
            }
        }
    }

    float* Hb = g_H + (size_t)idx * TT * FF;
    #pragma unroll
    for (int mi = 0; mi < 4; mi++) {
        int m = m0 + ty * 4 + mi;
        if (m >= Nt) continue;
        #pragma unroll
        for (int ni = 0; ni < 4; ni++) {
            float h1 = acc1[mi][ni];
            float h;
            if (act == 0) {
                float h2 = acc2[mi][ni];
                float sg = 1.f / (1.f + expf(-h2));
                h = h2 * sg * h2 * h1;                         // silu(h2)*h2*h1
            } else if (act == 1) {
                h = 0.5f * h1 * (1.f + erff(h1 * 0.70710678118654752f));  // exact gelu
            } else {
                h = fmaxf(h1, 0.f);
            }
            Hb[(size_t)m * FF + n0 + tx * 4 + ni] = h;
        }
    }
}

// GEMM2: Z = x_gathered + H @ W3    -> g_Z
__global__ void __launch_bounds__(256) gemm2_kernel(
    const float* __restrict__ x, const float* __restrict__ W3)
{
    int idx = blockIdx.z;
    int Nt = g_cnt[idx];
    int m0 = blockIdx.y * BM;
    if (m0 >= Nt) return;
    int n0 = blockIdx.x * BN;
    const float* Hb  = g_H + (size_t)idx * TT * FF;
    const float* W3b = W3  + (size_t)idx * FF * DD;

    __shared__ float As[BK][BM + 1];
    __shared__ float Bs[BK][BN];
    __shared__ int   stok[BM];
    int tid = threadIdx.x;
    if (tid < BM) {
        int m = m0 + tid;
        stok[tid] = (m < Nt) ? g_tok[idx * TT + m] : 0;
    }
    float acc[4][4] = {};
    int ty = tid >> 4, tx = tid & 15;

    for (int k0 = 0; k0 < FF; k0 += BK) {
        __syncthreads();
        #pragma unroll
        for (int it = 0; it < 4; it++) {
            int m = (tid >> 4) + it * 16;
            int k = tid & 15;
            int mm = m0 + m;
            As[k][m] = (mm < Nt) ? Hb[(size_t)mm * FF + k0 + k] : 0.f;
        }
        #pragma unroll
        for (int it = 0; it < 4; it++) {
            int k = (tid >> 6) + it * 4;
            int n = tid & 63;
            Bs[k][n] = W3b[(size_t)(k0 + k) * DD + n0 + n];
        }
        __syncthreads();
        #pragma unroll
        for (int k = 0; k < BK; k++) {
            float a[4], b[4];
            #pragma unroll
            for (int i = 0; i < 4; i++) a[i] = As[k][ty * 4 + i];
            #pragma unroll
            for (int i = 0; i < 4; i++) b[i] = Bs[k][tx * 4 + i];
            #pragma unroll
            for (int mi = 0; mi < 4; mi++)
                #pragma unroll
                for (int ni = 0; ni < 4; ni++)
                    acc[mi][ni] += a[mi] * b[ni];
        }
    }

    float* Zb = g_Z + (size_t)idx * TT * DD;
    #pragma unroll
    for (int mi = 0; mi < 4; mi++) {
        int m = ty * 4 + mi;
        int mm = m0 + m;
        if (mm >= Nt) continue;
        int tk = stok[m];
        #pragma unroll
        for (int ni = 0; ni < 4; ni++) {
            int n = n0 + tx * 4 + ni;
            Zb[(size_t)mm * DD + n] = acc[mi][ni] + x[(size_t)tk * DD + n];
        }
    }
}

// per-row output LayerNorm (in place on g_Z), with lout_g/lout_b of the expert
__global__ void expert_ln_kernel(const float* __restrict__ loutg,
                                 const float* __restrict__ loutb)
{
    int idx = blockIdx.y;
    int i = blockIdx.x;
    if (i >= g_cnt[idx]) return;
    float* z = g_Z + ((size_t)idx * TT + i) * DD;
    int tid = threadIdx.x;                    // 256
    __shared__ float rbuf[18];
    float v[4]; float s = 0.f, s2 = 0.f;
    #pragma unroll
    for (int r = 0; r < 4; r++) {
        int d = tid + 256 * r;
        v[r] = z[d]; s += v[r]; s2 += v[r] * v[r];
    }
    float mu, rs;
    block_meanvar_256(s, s2, rbuf, mu, rs);
    const float* gp = loutg + idx * DD;
    const float* bp = loutb + idx * DD;
    #pragma unroll
    for (int r = 0; r < 4; r++) {
        int d = tid + 256 * r;
        z[d] = (v[r] - mu) * rs * gp[d] + bp[d];
    }
}

// final: per token, per selected cluster: Oc = c0*y0 + c1*y1, cluster LN, gate-weighted sum
__global__ void final_kernel(const float* __restrict__ clng, const float* __restrict__ clnb,
                             float* __restrict__ out)
{
    int t = blockIdx.x;
    int tid = threadIdx.x;                    // 256
    __shared__ float rbuf[18];
    float o[4] = {};
    #pragma unroll
    for (int sI = 0; sI < 2; sI++) {
        int slot0 = g_islot[t * 4 + sI * 2 + 0];
        int slot1 = g_islot[t * 4 + sI * 2 + 1];
        int p0 = g_ipos[t * 4 + sI * 2 + 0];
        int p1 = g_ipos[t * 4 + sI * 2 + 1];
        float c0 = g_icoef[t * 4 + sI * 2 + 0];
        float c1 = g_icoef[t * 4 + sI * 2 + 1];
        const float* y0 = g_Z + ((size_t)slot0 * TT + p0) * DD;
        const float* y1 = g_Z + ((size_t)slot1 * TT + p1) * DD;
        float v[4], s = 0.f, s2 = 0.f;
        #pragma unroll
        for (int r = 0; r < 4; r++) {
            int d = tid + 256 * r;
            v[r] = c0 * y0[d] + c1 * y1[d];
            s += v[r]; s2 += v[r] * v[r];
        }
        float mu, rs;
        block_meanvar_256(s, s2, rbuf, mu, rs);
        int cc = g_sel[t * 2 + sI];
        float gt = g_gate[t * 2 + sI];
        #pragma unroll
        for (int r = 0; r < 4; r++) {
            int d = tid + 256 * r;
            o[r] += gt * ((v[r] - mu) * rs * clng[cc * DD + d] + clnb[cc * DD + d]);
        }
    }
    #pragma unroll
    for (int r = 0; r < 4; r++)
        out[(size_t)t * DD + tid + 256 * r] = o[r];
}

// ---------------- launcher ----------------
extern "C" void kernel_launch(void* const* d_in, const int* in_sizes, int n_in,
                              void* d_out, int out_size)
{
    const float* x     = (const float*)d_in[0];
    const float* W1    = (const float*)d_in[1];
    const float* W2    = (const float*)d_in[2];
    const float* W3    = (const float*)d_in[3];
    const float* ling  = (const float*)d_in[4];
    const float* linb  = (const float*)d_in[5];
    const float* loutg = (const float*)d_in[6];
    const float* loutb = (const float*)d_in[7];
    const float* clng  = (const float*)d_in[8];
    const float* clnb  = (const float*)d_in[9];
    const float* Wrc   = (const float*)d_in[10];
    const float* brc   = (const float*)d_in[11];
    const float* Wre   = (const float*)d_in[12];
    const float* bre   = (const float*)d_in[13];
    float* out = (float*)d_out;

    zero_cnt_kernel<<<1, 32>>>();
    routing_kernel<<<TT, 128>>>(x, Wrc, brc, Wre, bre);

    dim3 g1(FF / BN, TT / BM, NEXP);
    gemm1_kernel<<<g1, 256>>>(x, W1, W2, ling, linb);

    dim3 g2(DD / BN, TT / BM, NEXP);
    gemm2_kernel<<<g2, 256>>>(x, W3);

    dim3 g5(TT, NEXP);
    expert_ln_kernel<<<g5, 256>>>(loutg, loutb);

    final_kernel<<<TT, 256>>>(clng, clnb, out);
}

// round 2
// speedup vs baseline: 2.0354x; 2.0354x over previous
#include <cuda_runtime.h>
#include <math.h>
#include <stdint.h>

// Problem constants
#define TT 2048
#define DD 1024
#define FF 2048
#define CC 4
#define EE 4
#define NEXP 16
#define EPSL 1e-5f

#define BM1 128
#define BN1 64
#define BKK 16

// ---------------- device scratch (static, no allocation) ----------------
__device__ float g_A[16ULL*2048ULL*1024ULL];   // LN'd gathered input rows (tf32-rounded)
__device__ float g_H[16ULL*2048ULL*2048ULL];   // activated hidden per expert slot (tf32-rounded)
__device__ float g_Z[16ULL*2048ULL*1024ULL];   // expert output rows (residual, then LN in place)
__device__ int   g_cnt[NEXP];
__device__ int   g_tok[NEXP*TT];
__device__ float g_mu[TT];
__device__ float g_rstd[TT];
__device__ int   g_sel[TT*2];
__device__ float g_gate[TT*2];
__device__ int   g_islot[TT*4];
__device__ int   g_ipos[TT*4];
__device__ float g_icoef[TT*4];

// ---------------- helpers ----------------
__device__ __forceinline__ float tf32r(float f) {
    uint32_t r;
    asm("cvt.rna.tf32.f32 %0, %1;" : "=r"(r) : "f"(f));
    return __uint_as_float(r);
}

__device__ __forceinline__ void mma_tf32(float* c, const uint32_t* a, const uint32_t* b) {
    asm volatile(
        "mma.sync.aligned.m16n8k8.row.col.f32.tf32.tf32.f32 "
        "{%0,%1,%2,%3}, {%4,%5,%6,%7}, {%8,%9}, {%0,%1,%2,%3};\n"
        : "+f"(c[0]), "+f"(c[1]), "+f"(c[2]), "+f"(c[3])
        : "r"(a[0]), "r"(a[1]), "r"(a[2]), "r"(a[3]), "r"(b[0]), "r"(b[1]));
}

__device__ __forceinline__ void block_meanvar_256(float s, float s2, float* rbuf,
                                                  float& mu, float& rs)
{
    int tid = threadIdx.x, lane = tid & 31, w = tid >> 5;
    __syncthreads();
    #pragma unroll
    for (int o = 16; o; o >>= 1) {
        s  += __shfl_down_sync(0xffffffffu, s,  o);
        s2 += __shfl_down_sync(0xffffffffu, s2, o);
    }
    if (lane == 0) { rbuf[w] = s; rbuf[8 + w] = s2; }
    __syncthreads();
    if (tid == 0) {
        float S = 0.f, S2 = 0.f;
        #pragma unroll
        for (int ww = 0; ww < 8; ww++) { S += rbuf[ww]; S2 += rbuf[8 + ww]; }
        float m = S / (float)DD;
        rbuf[16] = m;
        rbuf[17] = rsqrtf(S2 / (float)DD - m * m + EPSL);
    }
    __syncthreads();
    mu = rbuf[16];
    rs = rbuf[17];
}

// ---------------- kernels ----------------
__global__ void zero_cnt_kernel()
{
    if (threadIdx.x < NEXP) g_cnt[threadIdx.x] = 0;
}

__global__ void routing_kernel(const float* __restrict__ x,
                               const float* __restrict__ Wrc, const float* __restrict__ brc,
                               const float* __restrict__ Wre, const float* __restrict__ bre)
{
    int t = blockIdx.x;
    __shared__ float xs[DD];
    __shared__ float rbuf[16];
    __shared__ float lgs[20];
    int tid = threadIdx.x;          // 128 threads
    int lane = tid & 31, wid = tid >> 5;

    float s = 0.f, s2 = 0.f;
    for (int d = tid; d < DD; d += 128) {
        float v = x[(size_t)t * DD + d];
        xs[d] = v; s += v; s2 += v * v;
    }
    #pragma unroll
    for (int o = 16; o; o >>= 1) {
        s  += __shfl_down_sync(0xffffffffu, s,  o);
        s2 += __shfl_down_sync(0xffffffffu, s2, o);
    }
    if (lane == 0) { rbuf[wid] = s; rbuf[8 + wid] = s2; }
    __syncthreads();
    if (tid == 0) {
        float S  = rbuf[0] + rbuf[1] + rbuf[2] + rbuf[3];
        float S2 = rbuf[8] + rbuf[9] + rbuf[10] + rbuf[11];
        float mu = S / (float)DD;
        float var = S2 / (float)DD - mu * mu;
        g_mu[t] = mu;
        g_rstd[t] = rsqrtf(var + EPSL);
    }

    for (int v = wid; v < 20; v += 4) {
        float acc = 0.f;
        if (v < CC) {
            for (int d = lane; d < DD; d += 32) acc += xs[d] * Wrc[d * CC + v];
        } else {
            int cc = (v - 4) >> 2, e = (v - 4) & 3;
            const float* wp = Wre + (size_t)cc * DD * EE + e;
            for (int d = lane; d < DD; d += 32) acc += xs[d] * wp[d * EE];
        }
        #pragma unroll
        for (int o = 16; o; o >>= 1) acc += __shfl_down_sync(0xffffffffu, acc, o);
        if (lane == 0) lgs[v] = acc;
    }
    __syncthreads();

    if (tid == 0) {
        float p[CC];
        float mx = -1e30f;
        for (int c = 0; c < CC; c++) { p[c] = lgs[c] + brc[c]; mx = fmaxf(mx, p[c]); }
        float ss = 0.f;
        for (int c = 0; c < CC; c++) { p[c] = expf(p[c] - mx); ss += p[c]; }
        for (int c = 0; c < CC; c++) p[c] /= ss;
        int i0 = 0;
        for (int c = 1; c < CC; c++) if (p[c] > p[i0]) i0 = c;
        int i1 = -1;
        for (int c = 0; c < CC; c++) if (c != i0 && (i1 < 0 || p[c] > p[i1])) i1 = c;
        float swt = p[i0] + p[i1];
        int sel[2] = { i0, i1 };
        float gv[2] = { p[i0] / swt, p[i1] / swt };

        for (int sI = 0; sI < 2; sI++) {
            int cc = sel[sI];
            g_sel[t * 2 + sI]  = cc;
            g_gate[t * 2 + sI] = gv[sI];
            float el[EE];
            for (int e = 0; e < EE; e++) el[e] = lgs[4 + cc * 4 + e] + bre[cc * EE + e];
            int e0 = 0;
            for (int e = 1; e < EE; e++) if (el[e] > el[e0]) e0 = e;
            int e1 = -1;
            for (int e = 0; e < EE; e++) if (e != e0 && (e1 < 0 || el[e] > el[e1])) e1 = e;
            float z = expf(el[e1] - el[e0]);
            float w0 = 1.f / (1.f + z), w1 = z / (1.f + z);
            int   eS[2] = { e0, e1 };
            float wS[2] = { w0, w1 };
            for (int q = 0; q < 2; q++) {
                int slot = cc * EE + eS[q];
                int pos = atomicAdd(&g_cnt[slot], 1);
                g_tok[slot * TT + pos] = t;
                g_islot[t * 4 + sI * 2 + q] = slot;
                g_ipos [t * 4 + sI * 2 + q] = pos;
                g_icoef[t * 4 + sI * 2 + q] = wS[q];
            }
        }
    }
}

// gather + input LayerNorm + tf32 rounding -> g_A
__global__ void prep_kernel(const float* __restrict__ x,
                            const float* __restrict__ ling, const float* __restrict__ linb)
{
    int idx = blockIdx.y;
    int i = blockIdx.x;
    if (i >= g_cnt[idx]) return;
    int tok = g_tok[idx * TT + i];
    float mu = g_mu[tok], rs = g_rstd[tok];
    const float4* xr = (const float4*)(x + (size_t)tok * DD);
    const float4* gp = (const float4*)(ling + (size_t)idx * DD);
    const float4* bp = (const float4*)(linb + (size_t)idx * DD);
    float4* ar = (float4*)(g_A + ((size_t)idx * TT + i) * DD);
    int d = threadIdx.x;           // 256 threads, 1 float4 each
    float4 xv = xr[d], gv = gp[d], bv = bp[d];
    float4 o;
    o.x = tf32r((xv.x - mu) * rs * gv.x + bv.x);
    o.y = tf32r((xv.y - mu) * rs * gv.y + bv.y);
    o.z = tf32r((xv.z - mu) * rs * gv.z + bv.z);
    o.w = tf32r((xv.w - mu) * rs * gv.w + bv.w);
    ar[d] = o;
}

// GEMM1: H = act( A @ W1 [, @ W2] ) using tf32 mma. DUAL = swiglu experts.
template<bool DUAL>
__global__ void __launch_bounds__(256) gemm1_mma_kernel(
    const float* __restrict__ W1, const float* __restrict__ W2)
{
    int z = blockIdx.z;
    int idx = DUAL ? ((z >> 1) * 4 + ((z & 1) ? 3 : 0))
                   : ((z >> 1) * 4 + ((z & 1) ? 2 : 1));
    int Nt = g_cnt[idx];
    int m0 = blockIdx.y * BM1;
    if (m0 >= Nt) return;
    int n0 = blockIdx.x * BN1;
    int act = (idx & 3) % 3;
    const float* W1b = W1 + (size_t)idx * DD * FF;
    const float* W2b = W2 + (size_t)idx * DD * FF;
    const float* Ab  = g_A + (size_t)idx * TT * DD;

    __shared__ float As[2][BM1][20];
    __shared__ float B1s[2][BKK][72];
    __shared__ float B2s[DUAL ? 2 : 1][BKK][72];

    int tid = threadIdx.x;
    int lane = tid & 31;
    int g = lane >> 2, tig = lane & 3;
    int w = tid >> 5, wm = w & 3, wn = w >> 2;

    int arow = tid >> 2;            // 0..63
    int acol = (tid & 3) << 2;      // 0,4,8,12
    int brow = tid >> 4;            // 0..15
    int bcol = (tid & 15) << 2;     // 0..60

    float acc1[2][4][4] = {};
    float acc2[DUAL ? 2 : 1][4][4] = {};

    float4 a0v, a1v, b1v, b2v;
    {
        const float* ap = Ab + (size_t)(m0 + arow) * DD + acol;
        a0v = *(const float4*)ap;
        a1v = *(const float4*)(ap + 64 * DD);
        b1v = *(const float4*)&W1b[(size_t)brow * FF + n0 + bcol];
        if (DUAL) b2v = *(const float4*)&W2b[(size_t)brow * FF + n0 + bcol];
    }

    const int NIT = DD / BKK;       // 64
    for (int it = 0; it < NIT; ++it) {
        int buf = it & 1;
        *(float4*)&As[buf][arow][acol] = a0v;
        *(float4*)&As[buf][arow + 64][acol] = a1v;
        {
            float4 t1;
            t1.x = tf32r(b1v.x); t1.y = tf32r(b1v.y);
            t1.z = tf32r(b1v.z); t1.w = tf32r(b1v.w);
            *(float4*)&B1s[buf][brow][bcol] = t1;
        }
        if (DUAL) {
            float4 t2;
            t2.x = tf32r(b2v.x); t2.y = tf32r(b2v.y);
            t2.z = tf32r(b2v.z); t2.w = tf32r(b2v.w);
            *(float4*)&B2s[buf][brow][bcol] = t2;
        }
        __syncthreads();
        if (it + 1 < NIT) {
            int k0 = (it + 1) * BKK;
            const float* ap = Ab + (size_t)(m0 + arow) * DD + k0 + acol;
            a0v = *(const float4*)ap;
            a1v = *(const float4*)(ap + 64 * DD);
            b1v = *(const float4*)&W1b[(size_t)(k0 + brow) * FF + n0 + bcol];
            if (DUAL) b2v = *(const float4*)&W2b[(size_t)(k0 + brow) * FF + n0 + bcol];
        }
        #pragma unroll
        for (int s = 0; s < 2; ++s) {
            int kk = s * 8 + tig;
            uint32_t af[2][4];
            #pragma unroll
            for (int mi = 0; mi < 2; ++mi) {
                int r = wm * 32 + mi * 16 + g;
                af[mi][0] = __float_as_uint(As[buf][r    ][kk    ]);
                af[mi][1] = __float_as_uint(As[buf][r + 8][kk    ]);
                af[mi][2] = __float_as_uint(As[buf][r    ][kk + 4]);
                af[mi][3] = __float_as_uint(As[buf][r + 8][kk + 4]);
            }
            #pragma unroll
            for (int ni = 0; ni < 4; ++ni) {
                int n = wn * 32 + ni * 8 + g;
                uint32_t bf[2];
                bf[0] = __float_as_uint(B1s[buf][kk    ][n]);
                bf[1] = __float_as_uint(B1s[buf][kk + 4][n]);
                #pragma unroll
                for (int mi = 0; mi < 2; ++mi)
                    mma_tf32(acc1[mi][ni], af[mi], bf);
                if (DUAL) {
                    uint32_t bf2[2];
                    bf2[0] = __float_as_uint(B2s[buf][kk    ][n]);
                    bf2[1] = __float_as_uint(B2s[buf][kk + 4][n]);
                    #pragma unroll
                    for (int mi = 0; mi < 2; ++mi)
                        mma_tf32(acc2[mi][ni], af[mi], bf2);
                }
            }
        }
    }

    float* Hb = g_H + (size_t)idx * TT * FF;
    #pragma unroll
    for (int mi = 0; mi < 2; ++mi) {
        #pragma unroll
        for (int rr = 0; rr < 2; ++rr) {
            int m = m0 + wm * 32 + mi * 16 + g + rr * 8;
            if (m >= Nt) continue;
            float* hrow = Hb + (size_t)m * FF + n0 + wn * 32;
            #pragma unroll
            for (int ni = 0; ni < 4; ++ni) {
                #pragma unroll
                for (int cc = 0; cc < 2; ++cc) {
                    float h1 = acc1[mi][ni][rr * 2 + cc];
                    float h;
                    if (DUAL) {
                        float h2 = acc2[mi][ni][rr * 2 + cc];
                        float sg = 1.f / (1.f + expf(-h2));
                        h = h2 * sg * h2 * h1;                       // silu(h2)*h2*h1
                    } else if (act == 1) {
                        h = 0.5f * h1 * (1.f + erff(h1 * 0.70710678118654752f));
                    } else {
                        h = fmaxf(h1, 0.f);
                    }
                    hrow[ni * 8 + 2 * tig + cc] = tf32r(h);
                }
            }
        }
    }
}

// GEMM2: Z = x_gathered + H @ W3 using tf32 mma.
__global__ void __launch_bounds__(256) gemm2_mma_kernel(
    const float* __restrict__ x, const float* __restrict__ W3)
{
    int idx = blockIdx.z;
    int Nt = g_cnt[idx];
    int m0 = blockIdx.y * BM1;
    if (m0 >= Nt) return;
    int n0 = blockIdx.x * BN1;
    const float* Ab  = g_H + (size_t)idx * TT * FF;
    const float* W3b = W3  + (size_t)idx * FF * DD;

    __shared__ float As[2][BM1][20];
    __shared__ float Bs[2][BKK][72];
    __shared__ int   stok[BM1];

    int tid = threadIdx.x;
    int lane = tid & 31;
    int g = lane >> 2, tig = lane & 3;
    int w = tid >> 5, wm = w & 3, wn = w >> 2;

    int arow = tid >> 2;
    int acol = (tid & 3) << 2;
    int brow = tid >> 4;
    int bcol = (tid & 15) << 2;

    if (tid < BM1) {
        int m = m0 + tid;
        stok[tid] = (m < Nt) ? g_tok[idx * TT + m] : 0;
    }

    float acc[2][4][4] = {};

    float4 a0v, a1v, bv;
    {
        const float* ap = Ab + (size_t)(m0 + arow) * FF + acol;
        a0v = *(const float4*)ap;
        a1v = *(const float4*)(ap + 64 * FF);
        bv  = *(const float4*)&W3b[(size_t)brow * DD + n0 + bcol];
    }

    const int NIT = FF / BKK;       // 128
    for (int it = 0; it < NIT; ++it) {
        int buf = it & 1;
        *(float4*)&As[buf][arow][acol] = a0v;
        *(float4*)&As[buf][arow + 64][acol] = a1v;
        {
            float4 t1;
            t1.x = tf32r(bv.x); t1.y = tf32r(bv.y);
            t1.z = tf32r(bv.z); t1.w = tf32r(bv.w);
            *(float4*)&Bs[buf][brow][bcol] = t1;
        }
        __syncthreads();
        if (it + 1 < NIT) {
            int k0 = (it + 1) * BKK;
            const float* ap = Ab + (size_t)(m0 + arow) * FF + k0 + acol;
            a0v = *(const float4*)ap;
            a1v = *(const float4*)(ap + 64 * FF);
            bv  = *(const float4*)&W3b[(size_t)(k0 + brow) * DD + n0 + bcol];
        }
        #pragma unroll
        for (int s = 0; s < 2; ++s) {
            int kk = s * 8 + tig;
            uint32_t af[2][4];
            #pragma unroll
            for (int mi = 0; mi < 2; ++mi) {
                int r = wm * 32 + mi * 16 + g;
                af[mi][0] = __float_as_uint(As[buf][r    ][kk    ]);
                af[mi][1] = __float_as_uint(As[buf][r + 8][kk    ]);
                af[mi][2] = __float_as_uint(As[buf][r    ][kk + 4]);
                af[mi][3] = __float_as_uint(As[buf][r + 8][kk + 4]);
            }
            #pragma unroll
            for (int ni = 0; ni < 4; ++ni) {
                int n = wn * 32 + ni * 8 + g;
                uint32_t bf[2];
                bf[0] = __float_as_uint(Bs[buf][kk    ][n]);
                bf[1] = __float_as_uint(Bs[buf][kk + 4][n]);
                #pragma unroll
                for (int mi = 0; mi < 2; ++mi)
                    mma_tf32(acc[mi][ni], af[mi], bf);
            }
        }
    }

    float* Zb = g_Z + (size_t)idx * TT * DD;
    #pragma unroll
    for (int mi = 0; mi < 2; ++mi) {
        #pragma unroll
        for (int rr = 0; rr < 2; ++rr) {
            int mloc = wm * 32 + mi * 16 + g + rr * 8;
            int m = m0 + mloc;
            if (m >= Nt) continue;
            int tk = stok[mloc];
            const float* xr = x + (size_t)tk * DD + n0 + wn * 32;
            float* zrow = Zb + (size_t)m * DD + n0 + wn * 32;
            #pragma unroll
            for (int ni = 0; ni < 4; ++ni) {
                #pragma unroll
                for (int cc = 0; cc < 2; ++cc) {
                    int col = ni * 8 + 2 * tig + cc;
                    zrow[col] = acc[mi][ni][rr * 2 + cc] + xr[col];
                }
            }
        }
    }
}

// per-row output LayerNorm (in place on g_Z)
__global__ void expert_ln_kernel(const float* __restrict__ loutg,
                                 const float* __restrict__ loutb)
{
    int idx = blockIdx.y;
    int i = blockIdx.x;
    if (i >= g_cnt[idx]) return;
    float* z = g_Z + ((size_t)idx * TT + i) * DD;
    int tid = threadIdx.x;                    // 256
    __shared__ float rbuf[18];
    float v[4]; float s = 0.f, s2 = 0.f;
    #pragma unroll
    for (int r = 0; r < 4; r++) {
        int d = tid + 256 * r;
        v[r] = z[d]; s += v[r]; s2 += v[r] * v[r];
    }
    float mu, rs;
    block_meanvar_256(s, s2, rbuf, mu, rs);
    const float* gp = loutg + (size_t)idx * DD;
    const float* bp = loutb + (size_t)idx * DD;
    #pragma unroll
    for (int r = 0; r < 4; r++) {
        int d = tid + 256 * r;
        z[d] = (v[r] - mu) * rs * gp[d] + bp[d];
    }
}

// final combine: Oc = c0*y0 + c1*y1, cluster LN, gate-weighted sum
__global__ void final_kernel(const float* __restrict__ clng, const float* __restrict__ clnb,
                             float* __restrict__ out)
{
    int t = blockIdx.x;
    int tid = threadIdx.x;                    // 256
    __shared__ float rbuf[18];
    float o[4] = {};
    #pragma unroll
    for (int sI = 0; sI < 2; sI++) {
        int slot0 = g_islot[t * 4 + sI * 2 + 0];
        int slot1 = g_islot[t * 4 + sI * 2 + 1];
        int p0 = g_ipos[t * 4 + sI * 2 + 0];
        int p1 = g_ipos[t * 4 + sI * 2 + 1];
        float c0 = g_icoef[t * 4 + sI * 2 + 0];
        float c1 = g_icoef[t * 4 + sI * 2 + 1];
        const float* y0 = g_Z + ((size_t)slot0 * TT + p0) * DD;
        const float* y1 = g_Z + ((size_t)slot1 * TT + p1) * DD;
        float v[4], s = 0.f, s2 = 0.f;
        #pragma unroll
        for (int r = 0; r < 4; r++) {
            int d = tid + 256 * r;
            v[r] = c0 * y0[d] + c1 * y1[d];
            s += v[r]; s2 += v[r] * v[r];
        }
        float mu, rs;
        block_meanvar_256(s, s2, rbuf, mu, rs);
        int cc = g_sel[t * 2 + sI];
        float gt = g_gate[t * 2 + sI];
        #pragma unroll
        for (int r = 0; r < 4; r++) {
            int d = tid + 256 * r;
            o[r] += gt * ((v[r] - mu) * rs * clng[cc * DD + d] + clnb[cc * DD + d]);
        }
    }
    #pragma unroll
    for (int r = 0; r < 4; r++)
        out[(size_t)t * DD + tid + 256 * r] = o[r];
}

// ---------------- launcher ----------------
extern "C" void kernel_launch(void* const* d_in, const int* in_sizes, int n_in,
                              void* d_out, int out_size)
{
    const float* x     = (const float*)d_in[0];
    const float* W1    = (const float*)d_in[1];
    const float* W2    = (const float*)d_in[2];
    const float* W3    = (const float*)d_in[3];
    const float* ling  = (const float*)d_in[4];
    const float* linb  = (const float*)d_in[5];
    const float* loutg = (const float*)d_in[6];
    const float* loutb = (const float*)d_in[7];
    const float* clng  = (const float*)d_in[8];
    const float* clnb  = (const float*)d_in[9];
    const float* Wrc   = (const float*)d_in[10];
    const float* brc   = (const float*)d_in[11];
    const float* Wre   = (const float*)d_in[12];
    const float* bre   = (const float*)d_in[13];
    float* out = (float*)d_out;

    zero_cnt_kernel<<<1, 32>>>();
    routing_kernel<<<TT, 128>>>(x, Wrc, brc, Wre, bre);

    dim3 gp(TT, NEXP);
    prep_kernel<<<gp, 256>>>(x, ling, linb);

    dim3 g1(FF / BN1, TT / BM1, 8);      // 8 dual experts, 8 non-dual
    gemm1_mma_kernel<true ><<<g1, 256>>>(W1, W2);
    gemm1_mma_kernel<false><<<g1, 256>>>(W1, W2);

    dim3 g2(DD / BN1, TT / BM1, NEXP);
    gemm2_mma_kernel<<<g2, 256>>>(x, W3);

    dim3 g5(TT, NEXP);
    expert_ln_kernel<<<g5, 256>>>(loutg, loutb);

    final_kernel<<<TT, 256>>>(clng, clnb, out);
}

// round 3
// speedup vs baseline: 3.7318x; 1.8334x over previous
#include <cuda_runtime.h>
#include <math.h>
#include <stdint.h>

// Problem constants
#define TT 2048
#define DD 1024
#define FF 2048
#define CC 4
#define EE 4
#define NEXP 16
#define EPSL 1e-5f

#define BM1 128
#define BN1 64
#define BKK 16
#define NST 3
#define APAD 20
#define BPAD 72

// ---------------- device scratch (static, no allocation) ----------------
__device__ float g_A[16ULL*2048ULL*1024ULL];   // LN'd gathered input rows (tf32-rounded)
__device__ float g_H[16ULL*2048ULL*2048ULL];   // activated hidden per expert slot
__device__ float g_Z[16ULL*2048ULL*1024ULL];   // expert output rows
__device__ int   g_cnt[NEXP];
__device__ int   g_tok[NEXP*TT];
__device__ float g_mu[TT];
__device__ float g_rstd[TT];
__device__ int   g_sel[TT*2];
__device__ float g_gate[TT*2];
__device__ int   g_islot[TT*4];
__device__ int   g_ipos[TT*4];
__device__ float g_icoef[TT*4];

// ---------------- helpers ----------------
__device__ __forceinline__ float tf32r(float f) {
    uint32_t r;
    asm("cvt.rna.tf32.f32 %0, %1;" : "=r"(r) : "f"(f));
    return __uint_as_float(r);
}

__device__ __forceinline__ void mma_tf32(float* c, const uint32_t* a, const uint32_t* b) {
    asm volatile(
        "mma.sync.aligned.m16n8k8.row.col.f32.tf32.tf32.f32 "
        "{%0,%1,%2,%3}, {%4,%5,%6,%7}, {%8,%9}, {%0,%1,%2,%3};\n"
        : "+f"(c[0]), "+f"(c[1]), "+f"(c[2]), "+f"(c[3])
        : "r"(a[0]), "r"(a[1]), "r"(a[2]), "r"(a[3]), "r"(b[0]), "r"(b[1]));
}

__device__ __forceinline__ void cp16(uint32_t dst, const void* src) {
    asm volatile("cp.async.cg.shared.global [%0], [%1], 16;\n" :: "r"(dst), "l"(src));
}
__device__ __forceinline__ void cp_commit() {
    asm volatile("cp.async.commit_group;\n" ::: "memory");
}
__device__ __forceinline__ void cp_wait1() {
    asm volatile("cp.async.wait_group 1;\n" ::: "memory");
}

__device__ __forceinline__ void block_meanvar_256(float s, float s2, float* rbuf,
                                                  float& mu, float& rs)
{
    int tid = threadIdx.x, lane = tid & 31, w = tid >> 5;
    __syncthreads();
    #pragma unroll
    for (int o = 16; o; o >>= 1) {
        s  += __shfl_down_sync(0xffffffffu, s,  o);
        s2 += __shfl_down_sync(0xffffffffu, s2, o);
    }
    if (lane == 0) { rbuf[w] = s; rbuf[8 + w] = s2; }
    __syncthreads();
    if (tid == 0) {
        float S = 0.f, S2 = 0.f;
        #pragma unroll
        for (int ww = 0; ww < 8; ww++) { S += rbuf[ww]; S2 += rbuf[8 + ww]; }
        float m = S / (float)DD;
        rbuf[16] = m;
        rbuf[17] = rsqrtf(S2 / (float)DD - m * m + EPSL);
    }
    __syncthreads();
    mu = rbuf[16];
    rs = rbuf[17];
}

// ---------------- small kernels ----------------
__global__ void zero_cnt_kernel()
{
    if (threadIdx.x < NEXP) g_cnt[threadIdx.x] = 0;
}

__global__ void routing_kernel(const float* __restrict__ x,
                               const float* __restrict__ Wrc, const float* __restrict__ brc,
                               const float* __restrict__ Wre, const float* __restrict__ bre)
{
    int t = blockIdx.x;
    __shared__ float xs[DD];
    __shared__ float rbuf[16];
    __shared__ float lgs[20];
    int tid = threadIdx.x;          // 128 threads
    int lane = tid & 31, wid = tid >> 5;

    float s = 0.f, s2 = 0.f;
    for (int d = tid; d < DD; d += 128) {
        float v = x[(size_t)t * DD + d];
        xs[d] = v; s += v; s2 += v * v;
    }
    #pragma unroll
    for (int o = 16; o; o >>= 1) {
        s  += __shfl_down_sync(0xffffffffu, s,  o);
        s2 += __shfl_down_sync(0xffffffffu, s2, o);
    }
    if (lane == 0) { rbuf[wid] = s; rbuf[8 + wid] = s2; }
    __syncthreads();
    if (tid == 0) {
        float S  = rbuf[0] + rbuf[1] + rbuf[2] + rbuf[3];
        float S2 = rbuf[8] + rbuf[9] + rbuf[10] + rbuf[11];
        float mu = S / (float)DD;
        float var = S2 / (float)DD - mu * mu;
        g_mu[t] = mu;
        g_rstd[t] = rsqrtf(var + EPSL);
    }

    for (int v = wid; v < 20; v += 4) {
        float acc = 0.f;
        if (v < CC) {
            for (int d = lane; d < DD; d += 32) acc += xs[d] * Wrc[d * CC + v];
        } else {
            int cc = (v - 4) >> 2, e = (v - 4) & 3;
            const float* wp = Wre + (size_t)cc * DD * EE + e;
            for (int d = lane; d < DD; d += 32) acc += xs[d] * wp[d * EE];
        }
        #pragma unroll
        for (int o = 16; o; o >>= 1) acc += __shfl_down_sync(0xffffffffu, acc, o);
        if (lane == 0) lgs[v] = acc;
    }
    __syncthreads();

    if (tid == 0) {
        float p[CC];
        float mx = -1e30f;
        for (int c = 0; c < CC; c++) { p[c] = lgs[c] + brc[c]; mx = fmaxf(mx, p[c]); }
        float ss = 0.f;
        for (int c = 0; c < CC; c++) { p[c] = expf(p[c] - mx); ss += p[c]; }
        for (int c = 0; c < CC; c++) p[c] /= ss;
        int i0 = 0;
        for (int c = 1; c < CC; c++) if (p[c] > p[i0]) i0 = c;
        int i1 = -1;
        for (int c = 0; c < CC; c++) if (c != i0 && (i1 < 0 || p[c] > p[i1])) i1 = c;
        float swt = p[i0] + p[i1];
        int sel[2] = { i0, i1 };
        float gv[2] = { p[i0] / swt, p[i1] / swt };

        for (int sI = 0; sI < 2; sI++) {
            int cc = sel[sI];
            g_sel[t * 2 + sI]  = cc;
            g_gate[t * 2 + sI] = gv[sI];
            float el[EE];
            for (int e = 0; e < EE; e++) el[e] = lgs[4 + cc * 4 + e] + bre[cc * EE + e];
            int e0 = 0;
            for (int e = 1; e < EE; e++) if (el[e] > el[e0]) e0 = e;
            int e1 = -1;
            for (int e = 0; e < EE; e++) if (e != e0 && (e1 < 0 || el[e] > el[e1])) e1 = e;
            float z = expf(el[e1] - el[e0]);
            float w0 = 1.f / (1.f + z), w1 = z / (1.f + z);
            int   eS[2] = { e0, e1 };
            float wS[2] = { w0, w1 };
            for (int q = 0; q < 2; q++) {
                int slot = cc * EE + eS[q];
                int pos = atomicAdd(&g_cnt[slot], 1);
                g_tok[slot * TT + pos] = t;
                g_islot[t * 4 + sI * 2 + q] = slot;
                g_ipos [t * 4 + sI * 2 + q] = pos;
                g_icoef[t * 4 + sI * 2 + q] = wS[q];
            }
        }
    }
}

// gather + input LayerNorm + tf32 rounding -> g_A
__global__ void prep_kernel(const float* __restrict__ x,
                            const float* __restrict__ ling, const float* __restrict__ linb)
{
    int idx = blockIdx.y;
    int i = blockIdx.x;
    if (i >= g_cnt[idx]) return;
    int tok = g_tok[idx * TT + i];
    float mu = g_mu[tok], rs = g_rstd[tok];
    const float4* xr = (const float4*)(x + (size_t)tok * DD);
    const float4* gp = (const float4*)(ling + (size_t)idx * DD);
    const float4* bp = (const float4*)(linb + (size_t)idx * DD);
    float4* ar = (float4*)(g_A + ((size_t)idx * TT + i) * DD);
    int d = threadIdx.x;           // 256 threads, 1 float4 each
    float4 xv = xr[d], gv = gp[d], bv = bp[d];
    float4 o;
    o.x = tf32r((xv.x - mu) * rs * gv.x + bv.x);
    o.y = tf32r((xv.y - mu) * rs * gv.y + bv.y);
    o.z = tf32r((xv.z - mu) * rs * gv.z + bv.z);
    o.w = tf32r((xv.w - mu) * rs * gv.w + bv.w);
    ar[d] = o;
}

// GEMM1: H = act( A @ W1 [, @ W2] ) using tf32 mma + cp.async 3-stage pipeline.
template<bool DUAL>
__global__ void __launch_bounds__(256, DUAL ? 2 : 3) gemm1_mma_kernel(
    const float* __restrict__ W1, const float* __restrict__ W2)
{
    int z = blockIdx.z;
    int idx = DUAL ? ((z >> 1) * 4 + ((z & 1) ? 3 : 0))
                   : ((z >> 1) * 4 + ((z & 1) ? 2 : 1));
    int Nt = g_cnt[idx];
    int m0 = blockIdx.y * BM1;
    if (m0 >= Nt) return;
    int n0 = blockIdx.x * BN1;
    int act = (idx & 3) % 3;
    const float* W1b = W1 + (size_t)idx * DD * FF;
    const float* W2b = W2 + (size_t)idx * DD * FF;
    const float* Ab  = g_A + (size_t)idx * TT * DD;

    extern __shared__ float smem[];
    float (*As)[BM1][APAD]  = (float (*)[BM1][APAD])smem;
    float (*B1s)[BKK][BPAD] = (float (*)[BKK][BPAD])(smem + NST * BM1 * APAD);
    float (*B2s)[BKK][BPAD] = (float (*)[BKK][BPAD])(smem + NST * BM1 * APAD + NST * BKK * BPAD);

    int tid = threadIdx.x;
    int lane = tid & 31;
    int g = lane >> 2, tig = lane & 3;
    int w = tid >> 5, wm = w & 3, wn = w >> 2;

    // cp.async indexing
    int ar0 = tid >> 2,          ac0 = (tid & 3) << 2;   // A transfer 0
    int ar1 = (tid + 256) >> 2,  ac1 = ac0;              // A transfer 1
    int brr = tid >> 4,          bcc = (tid & 15) << 2;  // B transfer

    float acc1[2][4][4] = {};
    float acc2[DUAL ? 2 : 1][4][4] = {};

    auto issue = [&](int st, int k0) {
        cp16((uint32_t)__cvta_generic_to_shared(&As[st][ar0][ac0]),
             Ab + (size_t)(m0 + ar0) * DD + k0 + ac0);
        cp16((uint32_t)__cvta_generic_to_shared(&As[st][ar1][ac1]),
             Ab + (size_t)(m0 + ar1) * DD + k0 + ac1);
        cp16((uint32_t)__cvta_generic_to_shared(&B1s[st][brr][bcc]),
             W1b + (size_t)(k0 + brr) * FF + n0 + bcc);
        if (DUAL)
            cp16((uint32_t)__cvta_generic_to_shared(&B2s[st][brr][bcc]),
                 W2b + (size_t)(k0 + brr) * FF + n0 + bcc);
    };

    const int NIT = DD / BKK;       // 64
    issue(0, 0);          cp_commit();
    issue(1, BKK);        cp_commit();

    for (int it = 0; it < NIT; ++it) {
        cp_wait1();
        __syncthreads();
        int buf = it % NST;
        #pragma unroll
        for (int s = 0; s < 2; ++s) {
            int kk = s * 8 + tig;
            uint32_t af[2][4];
            #pragma unroll
            for (int mi = 0; mi < 2; ++mi) {
                int r = wm * 32 + mi * 16 + g;
                af[mi][0] = __float_as_uint(As[buf][r    ][kk    ]);
                af[mi][1] = __float_as_uint(As[buf][r + 8][kk    ]);
                af[mi][2] = __float_as_uint(As[buf][r    ][kk + 4]);
                af[mi][3] = __float_as_uint(As[buf][r + 8][kk + 4]);
            }
            #pragma unroll
            for (int ni = 0; ni < 4; ++ni) {
                int n = wn * 32 + ni * 8 + g;
                uint32_t bf[2];
                bf[0] = __float_as_uint(B1s[buf][kk    ][n]);
                bf[1] = __float_as_uint(B1s[buf][kk + 4][n]);
                #pragma unroll
                for (int mi = 0; mi < 2; ++mi)
                    mma_tf32(acc1[mi][ni], af[mi], bf);
                if (DUAL) {
                    uint32_t bf2[2];
                    bf2[0] = __float_as_uint(B2s[buf][kk    ][n]);
                    bf2[1] = __float_as_uint(B2s[buf][kk + 4][n]);
                    #pragma unroll
                    for (int mi = 0; mi < 2; ++mi)
                        mma_tf32(acc2[mi][ni], af[mi], bf2);
                }
            }
        }
        if (it + 2 < NIT) issue((it + 2) % NST, (it + 2) * BKK);
        cp_commit();
    }

    float* Hb = g_H + (size_t)idx * TT * FF;
    #pragma unroll
    for (int mi = 0; mi < 2; ++mi) {
        #pragma unroll
        for (int rr = 0; rr < 2; ++rr) {
            int m = m0 + wm * 32 + mi * 16 + g + rr * 8;
            if (m >= Nt) continue;
            float* hrow = Hb + (size_t)m * FF + n0 + wn * 32;
            #pragma unroll
            for (int ni = 0; ni < 4; ++ni) {
                #pragma unroll
                for (int cc = 0; cc < 2; ++cc) {
                    float h1 = acc1[mi][ni][rr * 2 + cc];
                    float h;
                    if (DUAL) {
                        float h2 = acc2[mi][ni][rr * 2 + cc];
                        float sg = 1.f / (1.f + expf(-h2));
                        h = h2 * sg * h2 * h1;                       // silu(h2)*h2*h1
                    } else if (act == 1) {
                        h = 0.5f * h1 * (1.f + erff(h1 * 0.70710678118654752f));
                    } else {
                        h = fmaxf(h1, 0.f);
                    }
                    hrow[ni * 8 + 2 * tig + cc] = h;
                }
            }
        }
    }
}

// GEMM2: Z = x_gathered + H @ W3 using tf32 mma + cp.async pipeline.
__global__ void __launch_bounds__(256, 3) gemm2_mma_kernel(
    const float* __restrict__ x, const float* __restrict__ W3)
{
    int idx = blockIdx.z;
    int Nt = g_cnt[idx];
    int m0 = blockIdx.y * BM1;
    if (m0 >= Nt) return;
    int n0 = blockIdx.x * BN1;
    const float* Ab  = g_H + (size_t)idx * TT * FF;
    const float* W3b = W3  + (size_t)idx * FF * DD;

    extern __shared__ float smem[];
    float (*As)[BM1][APAD] = (float (*)[BM1][APAD])smem;
    float (*Bs)[BKK][BPAD] = (float (*)[BKK][BPAD])(smem + NST * BM1 * APAD);
    __shared__ int stok[BM1];

    int tid = threadIdx.x;
    int lane = tid & 31;
    int g = lane >> 2, tig = lane & 3;
    int w = tid >> 5, wm = w & 3, wn = w >> 2;

    int ar0 = tid >> 2,          ac0 = (tid & 3) << 2;
    int ar1 = (tid + 256) >> 2,  ac1 = ac0;
    int brr = tid >> 4,          bcc = (tid & 15) << 2;

    if (tid < BM1) {
        int m = m0 + tid;
        stok[tid] = (m < Nt) ? g_tok[idx * TT + m] : 0;
    }

    float acc[2][4][4] = {};

    auto issue = [&](int st, int k0) {
        cp16((uint32_t)__cvta_generic_to_shared(&As[st][ar0][ac0]),
             Ab + (size_t)(m0 + ar0) * FF + k0 + ac0);
        cp16((uint32_t)__cvta_generic_to_shared(&As[st][ar1][ac1]),
             Ab + (size_t)(m0 + ar1) * FF + k0 + ac1);
        cp16((uint32_t)__cvta_generic_to_shared(&Bs[st][brr][bcc]),
             W3b + (size_t)(k0 + brr) * DD + n0 + bcc);
    };

    const int NIT = FF / BKK;       // 128
    issue(0, 0);    cp_commit();
    issue(1, BKK);  cp_commit();

    for (int it = 0; it < NIT; ++it) {
        cp_wait1();
        __syncthreads();
        int buf = it % NST;
        #pragma unroll
        for (int s = 0; s < 2; ++s) {
            int kk = s * 8 + tig;
            uint32_t af[2][4];
            #pragma unroll
            for (int mi = 0; mi < 2; ++mi) {
                int r = wm * 32 + mi * 16 + g;
                af[mi][0] = __float_as_uint(As[buf][r    ][kk    ]);
                af[mi][1] = __float_as_uint(As[buf][r + 8][kk    ]);
                af[mi][2] = __float_as_uint(As[buf][r    ][kk + 4]);
                af[mi][3] = __float_as_uint(As[buf][r + 8][kk + 4]);
            }
            #pragma unroll
            for (int ni = 0; ni < 4; ++ni) {
                int n = wn * 32 + ni * 8 + g;
                uint32_t bf[2];
                bf[0] = __float_as_uint(Bs[buf][kk    ][n]);
                bf[1] = __float_as_uint(Bs[buf][kk + 4][n]);
                #pragma unroll
                for (int mi = 0; mi < 2; ++mi)
                    mma_tf32(acc[mi][ni], af[mi], bf);
            }
        }
        if (it + 2 < NIT) issue((it + 2) % NST, (it + 2) * BKK);
        cp_commit();
    }

    float* Zb = g_Z + (size_t)idx * TT * DD;
    #pragma unroll
    for (int mi = 0; mi < 2; ++mi) {
        #pragma unroll
        for (int rr = 0; rr < 2; ++rr) {
            int mloc = wm * 32 + mi * 16 + g + rr * 8;
            int m = m0 + mloc;
            if (m >= Nt) continue;
            int tk = stok[mloc];
            const float* xr = x + (size_t)tk * DD + n0 + wn * 32;
            float* zrow = Zb + (size_t)m * DD + n0 + wn * 32;
            #pragma unroll
            for (int ni = 0; ni < 4; ++ni) {
                #pragma unroll
                for (int cc = 0; cc < 2; ++cc) {
                    int col = ni * 8 + 2 * tig + cc;
                    zrow[col] = acc[mi][ni][rr * 2 + cc] + xr[col];
                }
            }
        }
    }
}

// per-row output LayerNorm (in place on g_Z)
__global__ void expert_ln_kernel(const float* __restrict__ loutg,
                                 const float* __restrict__ loutb)
{
    int idx = blockIdx.y;
    int i = blockIdx.x;
    if (i >= g_cnt[idx]) return;
    float* z = g_Z + ((size_t)idx * TT + i) * DD;
    int tid = threadIdx.x;                    // 256
    __shared__ float rbuf[18];
    float v[4]; float s = 0.f, s2 = 0.f;
    #pragma unroll
    for (int r = 0; r < 4; r++) {
        int d = tid + 256 * r;
        v[r] = z[d]; s += v[r]; s2 += v[r] * v[r];
    }
    float mu, rs;
    block_meanvar_256(s, s2, rbuf, mu, rs);
    const float* gp = loutg + (size_t)idx * DD;
    const float* bp = loutb + (size_t)idx * DD;
    #pragma unroll
    for (int r = 0; r < 4; r++) {
        int d = tid + 256 * r;
        z[d] = (v[r] - mu) * rs * gp[d] + bp[d];
    }
}

// final combine: Oc = c0*y0 + c1*y1, cluster LN, gate-weighted sum
__global__ void final_kernel(const float* __restrict__ clng, const float* __restrict__ clnb,
                             float* __restrict__ out)
{
    int t = blockIdx.x;
    int tid = threadIdx.x;                    // 256
    __shared__ float rbuf[18];
    float o[4] = {};
    #pragma unroll
    for (int sI = 0; sI < 2; sI++) {
        int slot0 = g_islot[t * 4 + sI * 2 + 0];
        int slot1 = g_islot[t * 4 + sI * 2 + 1];
        int p0 = g_ipos[t * 4 + sI * 2 + 0];
        int p1 = g_ipos[t * 4 + sI * 2 + 1];
        float c0 = g_icoef[t * 4 + sI * 2 + 0];
        float c1 = g_icoef[t * 4 + sI * 2 + 1];
        const float* y0 = g_Z + ((size_t)slot0 * TT + p0) * DD;
        const float* y1 = g_Z + ((size_t)slot1 * TT + p1) * DD;
        float v[4], s = 0.f, s2 = 0.f;
        #pragma unroll
        for (int r = 0; r < 4; r++) {
            int d = tid + 256 * r;
            v[r] = c0 * y0[d] + c1 * y1[d];
            s += v[r]; s2 += v[r] * v[r];
        }
        float mu, rs;
        block_meanvar_256(s, s2, rbuf, mu, rs);
        int cc = g_sel[t * 2 + sI];
        float gt = g_gate[t * 2 + sI];
        #pragma unroll
        for (int r = 0; r < 4; r++) {
            int d = tid + 256 * r;
            o[r] += gt * ((v[r] - mu) * rs * clng[cc * DD + d] + clnb[cc * DD + d]);
        }
    }
    #pragma unroll
    for (int r = 0; r < 4; r++)
        out[(size_t)t * DD + tid + 256 * r] = o[r];
}

// ---------------- launcher ----------------
extern "C" void kernel_launch(void* const* d_in, const int* in_sizes, int n_in,
                              void* d_out, int out_size)
{
    const float* x     = (const float*)d_in[0];
    const float* W1    = (const float*)d_in[1];
    const float* W2    = (const float*)d_in[2];
    const float* W3    = (const float*)d_in[3];
    const float* ling  = (const float*)d_in[4];
    const float* linb  = (const float*)d_in[5];
    const float* loutg = (const float*)d_in[6];
    const float* loutb = (const float*)d_in[7];
    const float* clng  = (const float*)d_in[8];
    const float* clnb  = (const float*)d_in[9];
    const float* Wrc   = (const float*)d_in[10];
    const float* brc   = (const float*)d_in[11];
    const float* Wre   = (const float*)d_in[12];
    const float* bre   = (const float*)d_in[13];
    float* out = (float*)d_out;

    const int SM_DUAL = (NST * BM1 * APAD + 2 * NST * BKK * BPAD) * 4;  // 58368
    const int SM_SNGL = (NST * BM1 * APAD +     NST * BKK * BPAD) * 4;  // 44544

    cudaFuncSetAttribute(gemm1_mma_kernel<true>,
                         cudaFuncAttributeMaxDynamicSharedMemorySize, SM_DUAL);
    cudaFuncSetAttribute(gemm1_mma_kernel<false>,
                         cudaFuncAttributeMaxDynamicSharedMemorySize, SM_SNGL);
    cudaFuncSetAttribute(gemm2_mma_kernel,
                         cudaFuncAttributeMaxDynamicSharedMemorySize, SM_SNGL);

    zero_cnt_kernel<<<1, 32>>>();
    routing_kernel<<<TT, 128>>>(x, Wrc, brc, Wre, bre);

    dim3 gp(TT, NEXP);
    prep_kernel<<<gp, 256>>>(x, ling, linb);

    dim3 g1(FF / BN1, TT / BM1, 8);
    gemm1_mma_kernel<true ><<<g1, 256, SM_DUAL>>>(W1, W2);
    gemm1_mma_kernel<false><<<g1, 256, SM_SNGL>>>(W1, W2);

    dim3 g2(DD / BN1, TT / BM1, NEXP);
    gemm2_mma_kernel<<<g2, 256, SM_SNGL>>>(x, W3);

    dim3 g5(TT, NEXP);
    expert_ln_kernel<<<g5, 256>>>(loutg, loutb);

    final_kernel<<<TT, 256>>>(clng, clnb, out);
}

// round 4
// speedup vs baseline: 3.9608x; 1.0614x over previous
#include <cuda_runtime.h>
#include <math.h>
#include <stdint.h>

// Problem constants
#define TT 2048
#define DD 1024
#define FF 2048
#define CC 4
#define EE 4
#define NEXP 16
#define EPSL 1e-5f

#define BM1 128
#define BN1 128
#define BKK 32
#define NST 3
#define APAD 36
#define BPAD 136
#define NTH 512

// ---------------- device scratch (static, no allocation) ----------------
__device__ float g_A[16ULL*2048ULL*1024ULL];   // LN'd gathered input rows (tf32-rounded)
__device__ float g_H[16ULL*2048ULL*2048ULL];   // activated hidden per expert slot
__device__ float g_Z[16ULL*2048ULL*1024ULL];   // expert output rows (pre-LN, + residual)
__device__ int   g_cnt[NEXP];
__device__ int   g_tok[NEXP*TT];
__device__ float g_mu[TT];
__device__ float g_rstd[TT];
__device__ int   g_sel[TT*2];
__device__ float g_gate[TT*2];
__device__ int   g_islot[TT*4];
__device__ int   g_ipos[TT*4];
__device__ float g_icoef[TT*4];

// ---------------- helpers ----------------
__device__ __forceinline__ float tf32r(float f) {
    uint32_t r;
    asm("cvt.rna.tf32.f32 %0, %1;" : "=r"(r) : "f"(f));
    return __uint_as_float(r);
}

__device__ __forceinline__ void mma_tf32(float* c, const uint32_t* a, const uint32_t* b) {
    asm volatile(
        "mma.sync.aligned.m16n8k8.row.col.f32.tf32.tf32.f32 "
        "{%0,%1,%2,%3}, {%4,%5,%6,%7}, {%8,%9}, {%0,%1,%2,%3};\n"
        : "+f"(c[0]), "+f"(c[1]), "+f"(c[2]), "+f"(c[3])
        : "r"(a[0]), "r"(a[1]), "r"(a[2]), "r"(a[3]), "r"(b[0]), "r"(b[1]));
}

__device__ __forceinline__ void cp16(uint32_t dst, const void* src) {
    asm volatile("cp.async.cg.shared.global [%0], [%1], 16;\n" :: "r"(dst), "l"(src));
}
__device__ __forceinline__ void cp_commit() {
    asm volatile("cp.async.commit_group;\n" ::: "memory");
}
__device__ __forceinline__ void cp_wait1() {
    asm volatile("cp.async.wait_group 1;\n" ::: "memory");
}

// block reduction for mean/var over DD elements, blockDim = 256
__device__ __forceinline__ void block_meanvar_256(float s, float s2, float* rbuf,
                                                  float& mu, float& rs)
{
    int tid = threadIdx.x, lane = tid & 31, w = tid >> 5;
    __syncthreads();
    #pragma unroll
    for (int o = 16; o; o >>= 1) {
        s  += __shfl_down_sync(0xffffffffu, s,  o);
        s2 += __shfl_down_sync(0xffffffffu, s2, o);
    }
    if (lane == 0) { rbuf[w] = s; rbuf[8 + w] = s2; }
    __syncthreads();
    if (tid == 0) {
        float S = 0.f, S2 = 0.f;
        #pragma unroll
        for (int ww = 0; ww < 8; ww++) { S += rbuf[ww]; S2 += rbuf[8 + ww]; }
        float m = S / (float)DD;
        rbuf[16] = m;
        rbuf[17] = rsqrtf(S2 / (float)DD - m * m + EPSL);
    }
    __syncthreads();
    mu = rbuf[16];
    rs = rbuf[17];
}

// ---------------- small kernels ----------------
__global__ void zero_cnt_kernel()
{
    if (threadIdx.x < NEXP) g_cnt[threadIdx.x] = 0;
}

__global__ void routing_kernel(const float* __restrict__ x,
                               const float* __restrict__ Wrc, const float* __restrict__ brc,
                               const float* __restrict__ Wre, const float* __restrict__ bre)
{
    int t = blockIdx.x;
    __shared__ float xs[DD];
    __shared__ float rbuf[16];
    __shared__ float lgs[20];
    int tid = threadIdx.x;          // 128 threads
    int lane = tid & 31, wid = tid >> 5;

    float s = 0.f, s2 = 0.f;
    for (int d = tid; d < DD; d += 128) {
        float v = x[(size_t)t * DD + d];
        xs[d] = v; s += v; s2 += v * v;
    }
    #pragma unroll
    for (int o = 16; o; o >>= 1) {
        s  += __shfl_down_sync(0xffffffffu, s,  o);
        s2 += __shfl_down_sync(0xffffffffu, s2, o);
    }
    if (lane == 0) { rbuf[wid] = s; rbuf[8 + wid] = s2; }
    __syncthreads();
    if (tid == 0) {
        float S  = rbuf[0] + rbuf[1] + rbuf[2] + rbuf[3];
        float S2 = rbuf[8] + rbuf[9] + rbuf[10] + rbuf[11];
        float mu = S / (float)DD;
        float var = S2 / (float)DD - mu * mu;
        g_mu[t] = mu;
        g_rstd[t] = rsqrtf(var + EPSL);
    }

    for (int v = wid; v < 20; v += 4) {
        float acc = 0.f;
        if (v < CC) {
            for (int d = lane; d < DD; d += 32) acc += xs[d] * Wrc[d * CC + v];
        } else {
            int cc = (v - 4) >> 2, e = (v - 4) & 3;
            const float* wp = Wre + (size_t)cc * DD * EE + e;
            for (int d = lane; d < DD; d += 32) acc += xs[d] * wp[d * EE];
        }
        #pragma unroll
        for (int o = 16; o; o >>= 1) acc += __shfl_down_sync(0xffffffffu, acc, o);
        if (lane == 0) lgs[v] = acc;
    }
    __syncthreads();

    if (tid == 0) {
        float p[CC];
        float mx = -1e30f;
        for (int c = 0; c < CC; c++) { p[c] = lgs[c] + brc[c]; mx = fmaxf(mx, p[c]); }
        float ss = 0.f;
        for (int c = 0; c < CC; c++) { p[c] = expf(p[c] - mx); ss += p[c]; }
        for (int c = 0; c < CC; c++) p[c] /= ss;
        int i0 = 0;
        for (int c = 1; c < CC; c++) if (p[c] > p[i0]) i0 = c;
        int i1 = -1;
        for (int c = 0; c < CC; c++) if (c != i0 && (i1 < 0 || p[c] > p[i1])) i1 = c;
        float swt = p[i0] + p[i1];
        int sel[2] = { i0, i1 };
        float gv[2] = { p[i0] / swt, p[i1] / swt };

        for (int sI = 0; sI < 2; sI++) {
            int cc = sel[sI];
            g_sel[t * 2 + sI]  = cc;
            g_gate[t * 2 + sI] = gv[sI];
            float el[EE];
            for (int e = 0; e < EE; e++) el[e] = lgs[4 + cc * 4 + e] + bre[cc * EE + e];
            int e0 = 0;
            for (int e = 1; e < EE; e++) if (el[e] > el[e0]) e0 = e;
            int e1 = -1;
            for (int e = 0; e < EE; e++) if (e != e0 && (e1 < 0 || el[e] > el[e1])) e1 = e;
            float z = expf(el[e1] - el[e0]);
            float w0 = 1.f / (1.f + z), w1 = z / (1.f + z);
            int   eS[2] = { e0, e1 };
            float wS[2] = { w0, w1 };
            for (int q = 0; q < 2; q++) {
                int slot = cc * EE + eS[q];
                int pos = atomicAdd(&g_cnt[slot], 1);
                g_tok[slot * TT + pos] = t;
                g_islot[t * 4 + sI * 2 + q] = slot;
                g_ipos [t * 4 + sI * 2 + q] = pos;
                g_icoef[t * 4 + sI * 2 + q] = wS[q];
            }
        }
    }
}

// gather + input LayerNorm + tf32 rounding -> g_A
__global__ void prep_kernel(const float* __restrict__ x,
                            const float* __restrict__ ling, const float* __restrict__ linb)
{
    int idx = blockIdx.y;
    int i = blockIdx.x;
    if (i >= g_cnt[idx]) return;
    int tok = g_tok[idx * TT + i];
    float mu = g_mu[tok], rs = g_rstd[tok];
    const float4* xr = (const float4*)(x + (size_t)tok * DD);
    const float4* gp = (const float4*)(ling + (size_t)idx * DD);
    const float4* bp = (const float4*)(linb + (size_t)idx * DD);
    float4* ar = (float4*)(g_A + ((size_t)idx * TT + i) * DD);
    int d = threadIdx.x;           // 256 threads, 1 float4 each
    float4 xv = xr[d], gv = gp[d], bv = bp[d];
    float4 o;
    o.x = tf32r((xv.x - mu) * rs * gv.x + bv.x);
    o.y = tf32r((xv.y - mu) * rs * gv.y + bv.y);
    o.z = tf32r((xv.z - mu) * rs * gv.z + bv.z);
    o.w = tf32r((xv.w - mu) * rs * gv.w + bv.w);
    ar[d] = o;
}

// GEMM1: H = act( A @ W1 [, @ W2] ).  128x128 block, 512 threads, 16 warps.
template<bool DUAL>
__global__ void __launch_bounds__(NTH, 1) gemm1_mma_kernel(
    const float* __restrict__ W1, const float* __restrict__ W2)
{
    int z = blockIdx.z;
    int idx = DUAL ? ((z >> 1) * 4 + ((z & 1) ? 3 : 0))
                   : ((z >> 1) * 4 + ((z & 1) ? 2 : 1));
    int Nt = g_cnt[idx];
    int m0 = blockIdx.y * BM1;
    if (m0 >= Nt) return;
    int n0 = blockIdx.x * BN1;
    int act = (idx & 3) % 3;
    const float* W1b = W1 + (size_t)idx * DD * FF;
    const float* W2b = W2 + (size_t)idx * DD * FF;
    const float* Ab  = g_A + (size_t)idx * TT * DD;

    extern __shared__ float smem[];
    float (*As)[BM1][APAD]  = (float (*)[BM1][APAD])smem;
    float (*B1s)[BKK][BPAD] = (float (*)[BKK][BPAD])(smem + NST * BM1 * APAD);
    float (*B2s)[BKK][BPAD] = (float (*)[BKK][BPAD])(smem + NST * BM1 * APAD + NST * BKK * BPAD);

    int tid = threadIdx.x;
    int lane = tid & 31;
    int g = lane >> 2, tig = lane & 3;
    int w = tid >> 5, wm = w & 3, wn = w >> 2;   // 16 warps: 4x4

    // cp.async indexing: A chunk 128x32 floats (2 cp/thread), B chunk 32x128 (2 cp/thread each)
    int arow = tid >> 3, acol = (tid & 7) << 2;     // rows 0..63 (+64)
    int brr  = tid >> 4, bcc  = (tid & 15) << 2;    // rows 0..31, cols 0..60 (+64)

    float acc1[2][4][4] = {};
    float acc2[DUAL ? 2 : 1][4][4] = {};

    auto issue = [&](int st, int k0) {
        cp16((uint32_t)__cvta_generic_to_shared(&As[st][arow][acol]),
             Ab + (size_t)(m0 + arow) * DD + k0 + acol);
        cp16((uint32_t)__cvta_generic_to_shared(&As[st][arow + 64][acol]),
             Ab + (size_t)(m0 + arow + 64) * DD + k0 + acol);
        cp16((uint32_t)__cvta_generic_to_shared(&B1s[st][brr][bcc]),
             W1b + (size_t)(k0 + brr) * FF + n0 + bcc);
        cp16((uint32_t)__cvta_generic_to_shared(&B1s[st][brr][bcc + 64]),
             W1b + (size_t)(k0 + brr) * FF + n0 + bcc + 64);
        if (DUAL) {
            cp16((uint32_t)__cvta_generic_to_shared(&B2s[st][brr][bcc]),
                 W2b + (size_t)(k0 + brr) * FF + n0 + bcc);
            cp16((uint32_t)__cvta_generic_to_shared(&B2s[st][brr][bcc + 64]),
                 W2b + (size_t)(k0 + brr) * FF + n0 + bcc + 64);
        }
    };

    const int NIT = DD / BKK;       // 32
    issue(0, 0);          cp_commit();
    issue(1, BKK);        cp_commit();

    for (int it = 0; it < NIT; ++it) {
        cp_wait1();
        __syncthreads();
        int buf = it % NST;
        #pragma unroll
        for (int s = 0; s < 4; ++s) {
            int kk = s * 8 + tig;
            uint32_t af[2][4];
            #pragma unroll
            for (int mi = 0; mi < 2; ++mi) {
                int r = wm * 32 + mi * 16 + g;
                af[mi][0] = __float_as_uint(As[buf][r    ][kk    ]);
                af[mi][1] = __float_as_uint(As[buf][r + 8][kk    ]);
                af[mi][2] = __float_as_uint(As[buf][r    ][kk + 4]);
                af[mi][3] = __float_as_uint(As[buf][r + 8][kk + 4]);
            }
            #pragma unroll
            for (int ni = 0; ni < 4; ++ni) {
                int n = wn * 32 + ni * 8 + g;
                uint32_t bf[2];
                bf[0] = __float_as_uint(B1s[buf][kk    ][n]);
                bf[1] = __float_as_uint(B1s[buf][kk + 4][n]);
                #pragma unroll
                for (int mi = 0; mi < 2; ++mi)
                    mma_tf32(acc1[mi][ni], af[mi], bf);
                if (DUAL) {
                    uint32_t bf2[2];
                    bf2[0] = __float_as_uint(B2s[buf][kk    ][n]);
                    bf2[1] = __float_as_uint(B2s[buf][kk + 4][n]);
                    #pragma unroll
                    for (int mi = 0; mi < 2; ++mi)
                        mma_tf32(acc2[mi][ni], af[mi], bf2);
                }
            }
        }
        if (it + 2 < NIT) issue((it + 2) % NST, (it + 2) * BKK);
        cp_commit();
    }

    float* Hb = g_H + (size_t)idx * TT * FF;
    #pragma unroll
    for (int mi = 0; mi < 2; ++mi) {
        #pragma unroll
        for (int rr = 0; rr < 2; ++rr) {
            int m = m0 + wm * 32 + mi * 16 + g + rr * 8;
            if (m >= Nt) continue;
            float* hrow = Hb + (size_t)m * FF + n0 + wn * 32;
            #pragma unroll
            for (int ni = 0; ni < 4; ++ni) {
                #pragma unroll
                for (int cc = 0; cc < 2; ++cc) {
                    float h1 = acc1[mi][ni][rr * 2 + cc];
                    float h;
                    if (DUAL) {
                        float h2 = acc2[mi][ni][rr * 2 + cc];
                        float sg = 1.f / (1.f + expf(-h2));
                        h = h2 * sg * h2 * h1;                       // silu(h2)*h2*h1
                    } else if (act == 1) {
                        h = 0.5f * h1 * (1.f + erff(h1 * 0.70710678118654752f));
                    } else {
                        h = fmaxf(h1, 0.f);
                    }
                    hrow[ni * 8 + 2 * tig + cc] = h;
                }
            }
        }
    }
}

// GEMM2: Z = x_gathered + H @ W3.  128x128 block, 512 threads.
__global__ void __launch_bounds__(NTH, 1) gemm2_mma_kernel(
    const float* __restrict__ x, const float* __restrict__ W3)
{
    int idx = blockIdx.z;
    int Nt = g_cnt[idx];
    int m0 = blockIdx.y * BM1;
    if (m0 >= Nt) return;
    int n0 = blockIdx.x * BN1;
    const float* Ab  = g_H + (size_t)idx * TT * FF;
    const float* W3b = W3  + (size_t)idx * FF * DD;

    extern __shared__ float smem[];
    float (*As)[BM1][APAD] = (float (*)[BM1][APAD])smem;
    float (*Bs)[BKK][BPAD] = (float (*)[BKK][BPAD])(smem + NST * BM1 * APAD);
    __shared__ int stok[BM1];

    int tid = threadIdx.x;
    int lane = tid & 31;
    int g = lane >> 2, tig = lane & 3;
    int w = tid >> 5, wm = w & 3, wn = w >> 2;

    int arow = tid >> 3, acol = (tid & 7) << 2;
    int brr  = tid >> 4, bcc  = (tid & 15) << 2;

    if (tid < BM1) {
        int m = m0 + tid;
        stok[tid] = (m < Nt) ? g_tok[idx * TT + m] : 0;
    }

    float acc[2][4][4] = {};

    auto issue = [&](int st, int k0) {
        cp16((uint32_t)__cvta_generic_to_shared(&As[st][arow][acol]),
             Ab + (size_t)(m0 + arow) * FF + k0 + acol);
        cp16((uint32_t)__cvta_generic_to_shared(&As[st][arow + 64][acol]),
             Ab + (size_t)(m0 + arow + 64) * FF + k0 + acol);
        cp16((uint32_t)__cvta_generic_to_shared(&Bs[st][brr][bcc]),
             W3b + (size_t)(k0 + brr) * DD + n0 + bcc);
        cp16((uint32_t)__cvta_generic_to_shared(&Bs[st][brr][bcc + 64]),
             W3b + (size_t)(k0 + brr) * DD + n0 + bcc + 64);
    };

    const int NIT = FF / BKK;       // 64
    issue(0, 0);    cp_commit();
    issue(1, BKK);  cp_commit();

    for (int it = 0; it < NIT; ++it) {
        cp_wait1();
        __syncthreads();
        int buf = it % NST;
        #pragma unroll
        for (int s = 0; s < 4; ++s) {
            int kk = s * 8 + tig;
            uint32_t af[2][4];
            #pragma unroll
            for (int mi = 0; mi < 2; ++mi) {
                int r = wm * 32 + mi * 16 + g;
                af[mi][0] = __float_as_uint(As[buf][r    ][kk    ]);
                af[mi][1] = __float_as_uint(As[buf][r + 8][kk    ]);
                af[mi][2] = __float_as_uint(As[buf][r    ][kk + 4]);
                af[mi][3] = __float_as_uint(As[buf][r + 8][kk + 4]);
            }
            #pragma unroll
            for (int ni = 0; ni < 4; ++ni) {
                int n = wn * 32 + ni * 8 + g;
                uint32_t bf[2];
                bf[0] = __float_as_uint(Bs[buf][kk    ][n]);
                bf[1] = __float_as_uint(Bs[buf][kk + 4][n]);
                #pragma unroll
                for (int mi = 0; mi < 2; ++mi)
                    mma_tf32(acc[mi][ni], af[mi], bf);
            }
        }
        if (it + 2 < NIT) issue((it + 2) % NST, (it + 2) * BKK);
        cp_commit();
    }

    float* Zb = g_Z + (size_t)idx * TT * DD;
    #pragma unroll
    for (int mi = 0; mi < 2; ++mi) {
        #pragma unroll
        for (int rr = 0; rr < 2; ++rr) {
            int mloc = wm * 32 + mi * 16 + g + rr * 8;
            int m = m0 + mloc;
            if (m >= Nt) continue;
            int tk = stok[mloc];
            const float* xr = x + (size_t)tk * DD + n0 + wn * 32;
            float* zrow = Zb + (size_t)m * DD + n0 + wn * 32;
            #pragma unroll
            for (int ni = 0; ni < 4; ++ni) {
                #pragma unroll
                for (int cc = 0; cc < 2; ++cc) {
                    int col = ni * 8 + 2 * tig + cc;
                    zrow[col] = acc[mi][ni][rr * 2 + cc] + xr[col];
                }
            }
        }
    }
}

// fused: per-row expert LayerNorm + expert combine + cluster LN + gate sum
__global__ void final_kernel(const float* __restrict__ loutg, const float* __restrict__ loutb,
                             const float* __restrict__ clng, const float* __restrict__ clnb,
                             float* __restrict__ out)
{
    int t = blockIdx.x;
    int tid = threadIdx.x;                    // 256
    __shared__ float rbuf[18];
    float o[4] = {};
    #pragma unroll
    for (int sI = 0; sI < 2; sI++) {
        float vcmb[4] = {};
        #pragma unroll
        for (int q = 0; q < 2; q++) {
            int slot = g_islot[t * 4 + sI * 2 + q];
            int pos  = g_ipos [t * 4 + sI * 2 + q];
            float cf = g_icoef[t * 4 + sI * 2 + q];
            const float* y = g_Z + ((size_t)slot * TT + pos) * DD;
            const float* gp = loutg + (size_t)slot * DD;
            const float* bp = loutb + (size_t)slot * DD;
            float v[4], s = 0.f, s2 = 0.f;
            #pragma unroll
            for (int r = 0; r < 4; r++) {
                int d = tid + 256 * r;
                v[r] = y[d]; s += v[r]; s2 += v[r] * v[r];
            }
            float mu, rs;
            block_meanvar_256(s, s2, rbuf, mu, rs);
            #pragma unroll
            for (int r = 0; r < 4; r++) {
                int d = tid + 256 * r;
                vcmb[r] += cf * ((v[r] - mu) * rs * gp[d] + bp[d]);
            }
        }
        float s = 0.f, s2 = 0.f;
        #pragma unroll
        for (int r = 0; r < 4; r++) { s += vcmb[r]; s2 += vcmb[r] * vcmb[r]; }
        float mu, rs;
        block_meanvar_256(s, s2, rbuf, mu, rs);
        int cc = g_sel[t * 2 + sI];
        float gt = g_gate[t * 2 + sI];
        #pragma unroll
        for (int r = 0; r < 4; r++) {
            int d = tid + 256 * r;
            o[r] += gt * ((vcmb[r] - mu) * rs * clng[cc * DD + d] + clnb[cc * DD + d]);
        }
    }
    #pragma unroll
    for (int r = 0; r < 4; r++)
        out[(size_t)t * DD + tid + 256 * r] = o[r];
}

// ---------------- launcher ----------------
extern "C" void kernel_launch(void* const* d_in, const int* in_sizes, int n_in,
                              void* d_out, int out_size)
{
    const float* x     = (const float*)d_in[0];
    const float* W1    = (const float*)d_in[1];
    const float* W2    = (const float*)d_in[2];
    const float* W3    = (const float*)d_in[3];
    const float* ling  = (const float*)d_in[4];
    const float* linb  = (const float*)d_in[5];
    const float* loutg = (const float*)d_in[6];
    const float* loutb = (const float*)d_in[7];
    const float* clng  = (const float*)d_in[8];
    const float* clnb  = (const float*)d_in[9];
    const float* Wrc   = (const float*)d_in[10];
    const float* brc   = (const float*)d_in[11];
    const float* Wre   = (const float*)d_in[12];
    const float* bre   = (const float*)d_in[13];
    float* out = (float*)d_out;

    const int SM_DUAL = (NST * BM1 * APAD + 2 * NST * BKK * BPAD) * 4;  // 159744
    const int SM_SNGL = (NST * BM1 * APAD +     NST * BKK * BPAD) * 4;  // 107520

    cudaFuncSetAttribute(gemm1_mma_kernel<true>,
                         cudaFuncAttributeMaxDynamicSharedMemorySize, SM_DUAL);
    cudaFuncSetAttribute(gemm1_mma_kernel<false>,
                         cudaFuncAttributeMaxDynamicSharedMemorySize, SM_SNGL);
    cudaFuncSetAttribute(gemm2_mma_kernel,
                         cudaFuncAttributeMaxDynamicSharedMemorySize, SM_SNGL);

    zero_cnt_kernel<<<1, 32>>>();
    routing_kernel<<<TT, 128>>>(x, Wrc, brc, Wre, bre);

    dim3 gp(TT, NEXP);
    prep_kernel<<<gp, 256>>>(x, ling, linb);

    dim3 g1(FF / BN1, TT / BM1, 8);
    gemm1_mma_kernel<true ><<<g1, NTH, SM_DUAL>>>(W1, W2);
    gemm1_mma_kernel<false><<<g1, NTH, SM_SNGL>>>(W1, W2);

    dim3 g2(DD / BN1, TT / BM1, NEXP);
    gemm2_mma_kernel<<<g2, NTH, SM_SNGL>>>(x, W3);

    final_kernel<<<TT, 256>>>(loutg, loutb, clng, clnb, out);
}